// round 3
// baseline (speedup 1.0000x reference)
#include <cuda_runtime.h>

#define H      512
#define NC     64
#define NS     5
#define NQ     15
#define NROWS  1280

__device__ float g_att[NROWS * H];

__device__ __forceinline__ float tanh_approx(float x) {
    float y;
    asm("tanh.approx.f32 %0, %1;" : "=f"(y) : "f"(x));
    return y;
}

// ---------------------------------------------------------------------------
// Kernel 1: g_att[r][n] = sum_k X[r][k] * W[n][k] + b[n]
// 64(m) x 32(n) tile, 128 threads, 4x4 micro-tile, BK=16.
// 320 blocks -> multiple resident per SM, smooth tail on 148 SMs.
// ---------------------------------------------------------------------------
__global__ __launch_bounds__(128) void gemm_xwt(const float* __restrict__ X,
                                                const float* __restrict__ W,
                                                const float* __restrict__ bias) {
    __shared__ float As[16][68];   // [k][m] 64 rows (+4 pad)
    __shared__ float Bs[16][36];   // [k][n] 32 rows (+4 pad)
    const int t  = threadIdx.x;
    const int tx = t & 7;          // n: 8 x 4
    const int ty = t >> 3;         // m: 16 x 4
    const int m0 = blockIdx.y * 64;
    const int n0 = blockIdx.x * 32;

    const int lr = t >> 2;         // 0..31
    const int lk = (t & 3) << 2;   // 0,4,8,12

    float acc[4][4] = {};

    for (int kk = 0; kk < H; kk += 16) {
        // A: 64 rows x 16 k  (each thread: rows lr and lr+32)
        float4 a0 = *(const float4*)&X[(m0 + lr) * H + kk + lk];
        float4 a1 = *(const float4*)&X[(m0 + lr + 32) * H + kk + lk];
        // B: 32 rows x 16 k
        float4 bv = *(const float4*)&W[(n0 + lr) * H + kk + lk];
        As[lk + 0][lr] = a0.x; As[lk + 1][lr] = a0.y;
        As[lk + 2][lr] = a0.z; As[lk + 3][lr] = a0.w;
        As[lk + 0][lr + 32] = a1.x; As[lk + 1][lr + 32] = a1.y;
        As[lk + 2][lr + 32] = a1.z; As[lk + 3][lr + 32] = a1.w;
        Bs[lk + 0][lr] = bv.x; Bs[lk + 1][lr] = bv.y;
        Bs[lk + 2][lr] = bv.z; Bs[lk + 3][lr] = bv.w;
        __syncthreads();
        #pragma unroll
        for (int k = 0; k < 16; k++) {
            float4 a4 = *(const float4*)&As[k][ty << 2];
            float4 b4 = *(const float4*)&Bs[k][tx << 2];
            float ar[4] = {a4.x, a4.y, a4.z, a4.w};
            float br[4] = {b4.x, b4.y, b4.z, b4.w};
            #pragma unroll
            for (int i = 0; i < 4; i++)
                #pragma unroll
                for (int j = 0; j < 4; j++)
                    acc[i][j] = fmaf(ar[i], br[j], acc[i][j]);
        }
        __syncthreads();
    }

    #pragma unroll
    for (int i = 0; i < 4; i++) {
        const int r = m0 + (ty << 2) + i;
        #pragma unroll
        for (int j = 0; j < 4; j++) {
            const int n = n0 + (tx << 2) + j;
            g_att[r * H + n] = acc[i][j] + bias[n];
        }
    }
}

// ---------------------------------------------------------------------------
// Kernel 2: fused scores -> softmax -> proto -> dists.
// grid = (64 support-classes, 8 query-class groups), 256 threads (8 warps).
// Queries processed in chunks of 5 per warp; support vectors register-cached
// per h-slice and reused across the 5 queries (LDS traffic / 5).
// ---------------------------------------------------------------------------
__global__ __launch_bounds__(256, 2) void proto_attn(const float* __restrict__ X,
                                                     float* __restrict__ out) {
    const int c    = blockIdx.x;
    const int qb   = blockIdx.y;
    const int t    = threadIdx.x;
    const int warp = t >> 5;
    const int lane = t & 31;

    __shared__ float4 sA[NS * 128];   // s_att rows of class c
    __shared__ float4 sS[NS * 128];   // raw support rows of class c

    const float4* attv = (const float4*)g_att;
    const float4* xv   = (const float4*)X;

    for (int i = t; i < NS * 128; i += 256) {
        const int s   = i >> 7;
        const int off = i & 127;
        const int row = c * 20 + s;
        sA[i] = attv[row * 128 + off];
        sS[i] = xv[row * 128 + off];
    }
    __syncthreads();

    const int qc = qb * 8 + warp;

    #pragma unroll
    for (int chunk = 0; chunk < 3; chunk++) {
        const int j0 = chunk * 5;

        // ---- scores: acc[j][s] = sum_h tanh(q_att[j][h] * s_att[s][h]) ----
        float acc[5][NS] = {};
        #pragma unroll
        for (int i = 0; i < 4; i++) {
            float4 b[NS];
            #pragma unroll
            for (int s = 0; s < NS; s++) b[s] = sA[s * 128 + lane + i * 32];
            #pragma unroll
            for (int j = 0; j < 5; j++) {
                const int row = qc * 20 + NS + j0 + j;
                const float4 a = attv[row * 128 + lane + i * 32];
                #pragma unroll
                for (int s = 0; s < NS; s++) {
                    acc[j][s] += tanh_approx(a.x * b[s].x);
                    acc[j][s] += tanh_approx(a.y * b[s].y);
                    acc[j][s] += tanh_approx(a.z * b[s].z);
                    acc[j][s] += tanh_approx(a.w * b[s].w);
                }
            }
        }
        #pragma unroll
        for (int j = 0; j < 5; j++)
            #pragma unroll
            for (int s = 0; s < NS; s++)
                #pragma unroll
                for (int o = 16; o > 0; o >>= 1)
                    acc[j][s] += __shfl_xor_sync(0xffffffffu, acc[j][s], o);

        // ---- softmax over s (all lanes hold full sums) ----
        #pragma unroll
        for (int j = 0; j < 5; j++) {
            float m = acc[j][0];
            #pragma unroll
            for (int s = 1; s < NS; s++) m = fmaxf(m, acc[j][s]);
            float sum = 0.f;
            #pragma unroll
            for (int s = 0; s < NS; s++) { acc[j][s] = __expf(acc[j][s] - m); sum += acc[j][s]; }
            const float inv = __fdividef(1.0f, sum);
            #pragma unroll
            for (int s = 0; s < NS; s++) acc[j][s] *= inv;
        }

        // ---- proto & dist ----
        float d[5] = {};
        #pragma unroll
        for (int i = 0; i < 4; i++) {
            float4 sv[NS];
            #pragma unroll
            for (int s = 0; s < NS; s++) sv[s] = sS[s * 128 + lane + i * 32];
            #pragma unroll
            for (int j = 0; j < 5; j++) {
                const int row = qc * 20 + NS + j0 + j;
                const float4 qv = xv[row * 128 + lane + i * 32];
                float px = 0.f, py = 0.f, pz = 0.f, pw = 0.f;
                #pragma unroll
                for (int s = 0; s < NS; s++) {
                    px = fmaf(acc[j][s], sv[s].x, px);
                    py = fmaf(acc[j][s], sv[s].y, py);
                    pz = fmaf(acc[j][s], sv[s].z, pz);
                    pw = fmaf(acc[j][s], sv[s].w, pw);
                }
                const float dx = px - qv.x, dy = py - qv.y;
                const float dz = pz - qv.z, dw = pw - qv.w;
                d[j] += dx * dx + dy * dy + dz * dz + dw * dw;
            }
        }
        #pragma unroll
        for (int j = 0; j < 5; j++) {
            #pragma unroll
            for (int o = 16; o > 0; o >>= 1)
                d[j] += __shfl_xor_sync(0xffffffffu, d[j], o);
            if (lane == 0) {
                const int q = qc * NQ + j0 + j;
                out[q * NC + c] = d[j];
            }
        }
    }
}

extern "C" void kernel_launch(void* const* d_in, const int* in_sizes, int n_in,
                              void* d_out, int out_size) {
    const float* x = (const float*)d_in[0];
    const float* W = (const float*)d_in[1];
    const float* b = (const float*)d_in[2];
    float* out = (float*)d_out;

    gemm_xwt<<<dim3(H / 32, NROWS / 64), 128>>>(x, W, b);
    proto_attn<<<dim3(NC, 8), 256>>>(x, out);
}

// round 4
// speedup vs baseline: 1.1726x; 1.1726x over previous
#include <cuda_runtime.h>

#define H      512
#define NC     64
#define NS     5
#define NQ     15
#define NROWS  1280

__device__ float g_att[NROWS * H];

__device__ __forceinline__ float tanh_approx(float x) {
    float y;
    asm("tanh.approx.f32 %0, %1;" : "=f"(y) : "f"(x));
    return y;
}

// ---------------------------------------------------------------------------
// Kernel 1 (FROZEN from round 3: ~10us): g_att = X @ W^T + b
// 64(m) x 32(n) tile, 128 threads, 4x4 micro-tile, BK=16.
// ---------------------------------------------------------------------------
__global__ __launch_bounds__(128) void gemm_xwt(const float* __restrict__ X,
                                                const float* __restrict__ W,
                                                const float* __restrict__ bias) {
    __shared__ float As[16][68];
    __shared__ float Bs[16][36];
    const int t  = threadIdx.x;
    const int tx = t & 7;
    const int ty = t >> 3;
    const int m0 = blockIdx.y * 64;
    const int n0 = blockIdx.x * 32;
    const int lr = t >> 2;
    const int lk = (t & 3) << 2;

    float acc[4][4] = {};

    for (int kk = 0; kk < H; kk += 16) {
        float4 a0 = *(const float4*)&X[(m0 + lr) * H + kk + lk];
        float4 a1 = *(const float4*)&X[(m0 + lr + 32) * H + kk + lk];
        float4 bv = *(const float4*)&W[(n0 + lr) * H + kk + lk];
        As[lk + 0][lr] = a0.x; As[lk + 1][lr] = a0.y;
        As[lk + 2][lr] = a0.z; As[lk + 3][lr] = a0.w;
        As[lk + 0][lr + 32] = a1.x; As[lk + 1][lr + 32] = a1.y;
        As[lk + 2][lr + 32] = a1.z; As[lk + 3][lr + 32] = a1.w;
        Bs[lk + 0][lr] = bv.x; Bs[lk + 1][lr] = bv.y;
        Bs[lk + 2][lr] = bv.z; Bs[lk + 3][lr] = bv.w;
        __syncthreads();
        #pragma unroll
        for (int k = 0; k < 16; k++) {
            float4 a4 = *(const float4*)&As[k][ty << 2];
            float4 b4 = *(const float4*)&Bs[k][tx << 2];
            float ar[4] = {a4.x, a4.y, a4.z, a4.w};
            float br[4] = {b4.x, b4.y, b4.z, b4.w};
            #pragma unroll
            for (int i = 0; i < 4; i++)
                #pragma unroll
                for (int j = 0; j < 4; j++)
                    acc[i][j] = fmaf(ar[i], br[j], acc[i][j]);
        }
        __syncthreads();
    }

    #pragma unroll
    for (int i = 0; i < 4; i++) {
        const int r = m0 + (ty << 2) + i;
        #pragma unroll
        for (int j = 0; j < 4; j++) {
            const int n = n0 + (tx << 2) + j;
            g_att[r * H + n] = acc[i][j] + bias[n];
        }
    }
}

// ---------------------------------------------------------------------------
// Kernel 2: fused scores -> softmax -> proto -> dists.
// grid = (64, 8), 256 threads (8 warps). Queries in chunks of 3 per warp:
// support float4s register-cached per h-slice, reused across the 3 queries
// (LDS / 3 vs per-query) while staying well under the 128-reg cap (no spill).
// ---------------------------------------------------------------------------
__global__ __launch_bounds__(256) void proto_attn(const float* __restrict__ X,
                                                  float* __restrict__ out) {
    const int c    = blockIdx.x;
    const int qb   = blockIdx.y;
    const int t    = threadIdx.x;
    const int warp = t >> 5;
    const int lane = t & 31;

    __shared__ float4 sA[NS * 128];
    __shared__ float4 sS[NS * 128];

    const float4* attv = (const float4*)g_att;
    const float4* xv   = (const float4*)X;

    for (int i = t; i < NS * 128; i += 256) {
        const int s   = i >> 7;
        const int off = i & 127;
        const int row = c * 20 + s;
        sA[i] = attv[row * 128 + off];
        sS[i] = xv[row * 128 + off];
    }
    __syncthreads();

    const int qc = qb * 8 + warp;

    #pragma unroll
    for (int chunk = 0; chunk < 5; chunk++) {
        const int j0 = chunk * 3;

        // ---- scores: acc[j][s] = sum_h tanh(q_att[j][h] * s_att[s][h]) ----
        float acc[3][NS] = {};
        #pragma unroll
        for (int i = 0; i < 4; i++) {
            float4 b[NS];
            #pragma unroll
            for (int s = 0; s < NS; s++) b[s] = sA[s * 128 + lane + i * 32];
            #pragma unroll
            for (int j = 0; j < 3; j++) {
                const int row = qc * 20 + NS + j0 + j;
                const float4 a = attv[row * 128 + lane + i * 32];
                #pragma unroll
                for (int s = 0; s < NS; s++) {
                    acc[j][s] += tanh_approx(a.x * b[s].x);
                    acc[j][s] += tanh_approx(a.y * b[s].y);
                    acc[j][s] += tanh_approx(a.z * b[s].z);
                    acc[j][s] += tanh_approx(a.w * b[s].w);
                }
            }
        }
        #pragma unroll
        for (int j = 0; j < 3; j++)
            #pragma unroll
            for (int s = 0; s < NS; s++)
                #pragma unroll
                for (int o = 16; o > 0; o >>= 1)
                    acc[j][s] += __shfl_xor_sync(0xffffffffu, acc[j][s], o);

        // ---- softmax over s ----
        #pragma unroll
        for (int j = 0; j < 3; j++) {
            float m = acc[j][0];
            #pragma unroll
            for (int s = 1; s < NS; s++) m = fmaxf(m, acc[j][s]);
            float sum = 0.f;
            #pragma unroll
            for (int s = 0; s < NS; s++) { acc[j][s] = __expf(acc[j][s] - m); sum += acc[j][s]; }
            const float inv = __fdividef(1.0f, sum);
            #pragma unroll
            for (int s = 0; s < NS; s++) acc[j][s] *= inv;
        }

        // ---- proto & dist ----
        float d[3] = {};
        #pragma unroll
        for (int i = 0; i < 4; i++) {
            float4 sv[NS];
            #pragma unroll
            for (int s = 0; s < NS; s++) sv[s] = sS[s * 128 + lane + i * 32];
            #pragma unroll
            for (int j = 0; j < 3; j++) {
                const int row = qc * 20 + NS + j0 + j;
                const float4 qv = xv[row * 128 + lane + i * 32];
                float px = 0.f, py = 0.f, pz = 0.f, pw = 0.f;
                #pragma unroll
                for (int s = 0; s < NS; s++) {
                    px = fmaf(acc[j][s], sv[s].x, px);
                    py = fmaf(acc[j][s], sv[s].y, py);
                    pz = fmaf(acc[j][s], sv[s].z, pz);
                    pw = fmaf(acc[j][s], sv[s].w, pw);
                }
                const float dx = px - qv.x, dy = py - qv.y;
                const float dz = pz - qv.z, dw = pw - qv.w;
                d[j] += dx * dx + dy * dy + dz * dz + dw * dw;
            }
        }
        #pragma unroll
        for (int j = 0; j < 3; j++) {
            #pragma unroll
            for (int o = 16; o > 0; o >>= 1)
                d[j] += __shfl_xor_sync(0xffffffffu, d[j], o);
            if (lane == 0) {
                const int q = qc * NQ + j0 + j;
                out[q * NC + c] = d[j];
            }
        }
    }
}

extern "C" void kernel_launch(void* const* d_in, const int* in_sizes, int n_in,
                              void* d_out, int out_size) {
    const float* x = (const float*)d_in[0];
    const float* W = (const float*)d_in[1];
    const float* b = (const float*)d_in[2];
    float* out = (float*)d_out;

    gemm_xwt<<<dim3(H / 32, NROWS / 64), 128>>>(x, W, b);
    proto_attn<<<dim3(NC, 8), 256>>>(x, out);
}